// round 1
// baseline (speedup 1.0000x reference)
#include <cuda_runtime.h>
#include <math.h>

#define BATCH 4
#define SEQ   4096
#define DIM   1024
#define MTOT  (BATCH * SEQ)          // 16384
#define LN_EPS 1e-5f
#define SM_SCALE (1.0f / 32.0f)      // 1/sqrt(1024)

// ---------------------------------------------------------------------------
// Scratch (device globals: allocation-free rule)
// ---------------------------------------------------------------------------
__device__ float g_q[(size_t)BATCH * SEQ * DIM];   // 64 MB
__device__ float g_k[(size_t)BATCH * SEQ * DIM];   // 64 MB
__device__ float g_v[(size_t)BATCH * SEQ * DIM];   // 64 MB
__device__ float g_s[(size_t)BATCH * SEQ * SEQ];   // 256 MB (scores -> attn in place)
__device__ float g_att[(size_t)BATCH * SEQ * DIM]; // 64 MB

// ---------------------------------------------------------------------------
// NT GEMM: C[m,n] = alpha * sum_k A[m,k] * B[n,k]  (+ bias[n])
// A: [M,K] row-major, B: [N,K] row-major. 128x128 tile, K-step 8, 256 thr.
// ---------------------------------------------------------------------------
__global__ void __launch_bounds__(256)
gemm_nt_kernel(const float* __restrict__ A,
               const float* __restrict__ Bm,
               const float* __restrict__ bias,
               float* __restrict__ C,
               int Nn, int K, float alpha,
               size_t sA, size_t sB, size_t sC)
{
    __shared__ float As[8][128];
    __shared__ float Bs[8][128];

    const float* Ab = A  + blockIdx.z * sA;
    const float* Bb = Bm + blockIdx.z * sB;
    float*       Cb = C  + blockIdx.z * sC;

    const int tid = threadIdx.x;
    const int m0  = blockIdx.y * 128;
    const int n0  = blockIdx.x * 128;
    const int ty  = tid >> 4;          // 0..15
    const int tx  = tid & 15;          // 0..15
    const int lr  = tid >> 1;          // 0..127 (row within tile)
    const int lc  = (tid & 1) << 2;    // 0 or 4 (k offset)

    const float* Aptr = Ab + (size_t)(m0 + lr) * K + lc;
    const float* Bptr = Bb + (size_t)(n0 + lr) * K + lc;

    float acc[8][8];
#pragma unroll
    for (int i = 0; i < 8; ++i)
#pragma unroll
        for (int j = 0; j < 8; ++j) acc[i][j] = 0.f;

    float4 a = *(const float4*)(Aptr);
    float4 b = *(const float4*)(Bptr);

    for (int kt = 0; kt < K; kt += 8) {
        As[lc+0][lr] = a.x; As[lc+1][lr] = a.y; As[lc+2][lr] = a.z; As[lc+3][lr] = a.w;
        Bs[lc+0][lr] = b.x; Bs[lc+1][lr] = b.y; Bs[lc+2][lr] = b.z; Bs[lc+3][lr] = b.w;
        __syncthreads();

        if (kt + 8 < K) {                         // prefetch next k-tile
            a = *(const float4*)(Aptr + kt + 8);
            b = *(const float4*)(Bptr + kt + 8);
        }

#pragma unroll
        for (int kk = 0; kk < 8; ++kk) {
            float af[8], bf[8];
            *(float4*)&af[0] = *(const float4*)&As[kk][ty * 4];
            *(float4*)&af[4] = *(const float4*)&As[kk][ty * 4 + 64];
            *(float4*)&bf[0] = *(const float4*)&Bs[kk][tx * 4];
            *(float4*)&bf[4] = *(const float4*)&Bs[kk][tx * 4 + 64];
#pragma unroll
            for (int i = 0; i < 8; ++i)
#pragma unroll
                for (int j = 0; j < 8; ++j)
                    acc[i][j] = fmaf(af[i], bf[j], acc[i][j]);
        }
        __syncthreads();
    }

#pragma unroll
    for (int i = 0; i < 8; ++i) {
        const int m = m0 + ((i < 4) ? (ty * 4 + i) : (64 + ty * 4 + i - 4));
#pragma unroll
        for (int jg = 0; jg < 2; ++jg) {
            const int n = n0 + tx * 4 + jg * 64;
            float4 r;
            r.x = acc[i][jg*4+0] * alpha;
            r.y = acc[i][jg*4+1] * alpha;
            r.z = acc[i][jg*4+2] * alpha;
            r.w = acc[i][jg*4+3] * alpha;
            if (bias) {
                r.x += bias[n+0]; r.y += bias[n+1];
                r.z += bias[n+2]; r.w += bias[n+3];
            }
            *(float4*)(Cb + (size_t)m * Nn + n) = r;
        }
    }
}

// ---------------------------------------------------------------------------
// NN GEMM: C[m,n] = sum_k A[m,k] * B[k,n]
// A: [M,K] row-major, B: [K,N] row-major. Same tiling as NT.
// ---------------------------------------------------------------------------
__global__ void __launch_bounds__(256)
gemm_nn_kernel(const float* __restrict__ A,
               const float* __restrict__ Bm,
               float* __restrict__ C,
               int Nn, int K,
               size_t sA, size_t sB, size_t sC)
{
    __shared__ float As[8][128];
    __shared__ float Bs[8][128];

    const float* Ab = A  + blockIdx.z * sA;
    const float* Bb = Bm + blockIdx.z * sB;
    float*       Cb = C  + blockIdx.z * sC;

    const int tid = threadIdx.x;
    const int m0  = blockIdx.y * 128;
    const int n0  = blockIdx.x * 128;
    const int ty  = tid >> 4;
    const int tx  = tid & 15;
    const int lr  = tid >> 1;          // A-load row
    const int lc  = (tid & 1) << 2;    // A-load k offset
    const int br  = tid >> 5;          // B-load k-row 0..7
    const int bc  = (tid & 31) << 2;   // B-load col 0..124

    const float* Aptr = Ab + (size_t)(m0 + lr) * K + lc;
    const float* Bptr = Bb + (size_t)br * Nn + n0 + bc;

    float acc[8][8];
#pragma unroll
    for (int i = 0; i < 8; ++i)
#pragma unroll
        for (int j = 0; j < 8; ++j) acc[i][j] = 0.f;

    float4 a = *(const float4*)(Aptr);
    float4 b = *(const float4*)(Bptr);

    for (int kt = 0; kt < K; kt += 8) {
        As[lc+0][lr] = a.x; As[lc+1][lr] = a.y; As[lc+2][lr] = a.z; As[lc+3][lr] = a.w;
        *(float4*)&Bs[br][bc] = b;
        __syncthreads();

        if (kt + 8 < K) {
            a = *(const float4*)(Aptr + kt + 8);
            b = *(const float4*)(Bptr + (size_t)(kt + 8) * Nn);
        }

#pragma unroll
        for (int kk = 0; kk < 8; ++kk) {
            float af[8], bf[8];
            *(float4*)&af[0] = *(const float4*)&As[kk][ty * 4];
            *(float4*)&af[4] = *(const float4*)&As[kk][ty * 4 + 64];
            *(float4*)&bf[0] = *(const float4*)&Bs[kk][tx * 4];
            *(float4*)&bf[4] = *(const float4*)&Bs[kk][tx * 4 + 64];
#pragma unroll
            for (int i = 0; i < 8; ++i)
#pragma unroll
                for (int j = 0; j < 8; ++j)
                    acc[i][j] = fmaf(af[i], bf[j], acc[i][j]);
        }
        __syncthreads();
    }

#pragma unroll
    for (int i = 0; i < 8; ++i) {
        const int m = m0 + ((i < 4) ? (ty * 4 + i) : (64 + ty * 4 + i - 4));
#pragma unroll
        for (int jg = 0; jg < 2; ++jg) {
            const int n = n0 + tx * 4 + jg * 64;
            float4 r;
            r.x = acc[i][jg*4+0];
            r.y = acc[i][jg*4+1];
            r.z = acc[i][jg*4+2];
            r.w = acc[i][jg*4+3];
            *(float4*)(Cb + (size_t)m * Nn + n) = r;
        }
    }
}

// ---------------------------------------------------------------------------
// Row softmax over SEQ=4096, in place. One CTA per row, 256 threads,
// 16 elements per thread held in registers (single read + single write).
// ---------------------------------------------------------------------------
__global__ void __launch_bounds__(256)
softmax_kernel(float* __restrict__ S)
{
    __shared__ float sh[8];
    float* p = S + (size_t)blockIdx.x * SEQ;
    const int t    = threadIdx.x;
    const int lane = t & 31;
    const int wrp  = t >> 5;

    float4 v[4];
    float mx = -1e30f;
#pragma unroll
    for (int i = 0; i < 4; ++i) {
        v[i] = *(const float4*)(p + i * 1024 + t * 4);
        mx = fmaxf(mx, fmaxf(fmaxf(v[i].x, v[i].y), fmaxf(v[i].z, v[i].w)));
    }
#pragma unroll
    for (int o = 16; o > 0; o >>= 1)
        mx = fmaxf(mx, __shfl_xor_sync(0xffffffffu, mx, o));
    if (lane == 0) sh[wrp] = mx;
    __syncthreads();
    float m_all = sh[0];
#pragma unroll
    for (int w = 1; w < 8; ++w) m_all = fmaxf(m_all, sh[w]);
    __syncthreads();

    float sum = 0.f;
#pragma unroll
    for (int i = 0; i < 4; ++i) {
        v[i].x = __expf(v[i].x - m_all);
        v[i].y = __expf(v[i].y - m_all);
        v[i].z = __expf(v[i].z - m_all);
        v[i].w = __expf(v[i].w - m_all);
        sum += v[i].x + v[i].y + v[i].z + v[i].w;
    }
#pragma unroll
    for (int o = 16; o > 0; o >>= 1)
        sum += __shfl_xor_sync(0xffffffffu, sum, o);
    if (lane == 0) sh[wrp] = sum;
    __syncthreads();
    float s_all = 0.f;
#pragma unroll
    for (int w = 0; w < 8; ++w) s_all += sh[w];
    const float inv = 1.0f / s_all;

#pragma unroll
    for (int i = 0; i < 4; ++i) {
        float4 r;
        r.x = v[i].x * inv; r.y = v[i].y * inv;
        r.z = v[i].z * inv; r.w = v[i].w * inv;
        *(float4*)(p + i * 1024 + t * 4) = r;
    }
}

// ---------------------------------------------------------------------------
// Residual + LayerNorm over D=1024. One CTA per row, 256 threads, 4 el/thread.
// ---------------------------------------------------------------------------
__global__ void __launch_bounds__(256)
ln_kernel(const float* __restrict__ emb, const float* __restrict__ att,
          const float* __restrict__ gamma, const float* __restrict__ beta,
          float* __restrict__ out)
{
    __shared__ float shs[8];
    __shared__ float shq[8];
    const size_t base = (size_t)blockIdx.x * DIM;
    const int t    = threadIdx.x;
    const int lane = t & 31;
    const int wrp  = t >> 5;

    float4 e = *(const float4*)(emb + base + t * 4);
    float4 a = *(const float4*)(att + base + t * 4);
    float4 x;
    x.x = e.x + a.x; x.y = e.y + a.y; x.z = e.z + a.z; x.w = e.w + a.w;

    float s  = x.x + x.y + x.z + x.w;
    float sq = x.x*x.x + x.y*x.y + x.z*x.z + x.w*x.w;
#pragma unroll
    for (int o = 16; o > 0; o >>= 1) {
        s  += __shfl_xor_sync(0xffffffffu, s,  o);
        sq += __shfl_xor_sync(0xffffffffu, sq, o);
    }
    if (lane == 0) { shs[wrp] = s; shq[wrp] = sq; }
    __syncthreads();
    s = 0.f; sq = 0.f;
#pragma unroll
    for (int w = 0; w < 8; ++w) { s += shs[w]; sq += shq[w]; }

    const float mu   = s * (1.0f / (float)DIM);
    const float var  = sq * (1.0f / (float)DIM) - mu * mu;
    const float rstd = rsqrtf(var + LN_EPS);

    float4 g  = *(const float4*)(gamma + t * 4);
    float4 bt = *(const float4*)(beta  + t * 4);
    float4 r;
    r.x = g.x * (x.x - mu) * rstd + bt.x;
    r.y = g.y * (x.y - mu) * rstd + bt.y;
    r.z = g.z * (x.z - mu) * rstd + bt.z;
    r.w = g.w * (x.w - mu) * rstd + bt.w;
    *(float4*)(out + base + t * 4) = r;
}

// ---------------------------------------------------------------------------
// Launch
// ---------------------------------------------------------------------------
extern "C" void kernel_launch(void* const* d_in, const int* in_sizes, int n_in,
                              void* d_out, int out_size)
{
    (void)in_sizes; (void)n_in; (void)out_size;
    const float* emb   = (const float*)d_in[0];
    // d_in[1..3] = edge_indices / edge_times / timestamps (unused by forward)
    const float* Wq    = (const float*)d_in[4];
    const float* bq    = (const float*)d_in[5];
    const float* Wk    = (const float*)d_in[6];
    const float* bk    = (const float*)d_in[7];
    const float* Wv    = (const float*)d_in[8];
    const float* bv    = (const float*)d_in[9];
    const float* gamma = (const float*)d_in[10];
    const float* beta  = (const float*)d_in[11];
    float* out = (float*)d_out;

    float *q, *k, *v, *s, *att;
    cudaGetSymbolAddress((void**)&q,   g_q);
    cudaGetSymbolAddress((void**)&k,   g_k);
    cudaGetSymbolAddress((void**)&v,   g_v);
    cudaGetSymbolAddress((void**)&s,   g_s);
    cudaGetSymbolAddress((void**)&att, g_att);

    const dim3 blk(256);

    // QKV projections: [16384,1024] x [1024,1024]^T + bias
    const dim3 gqkv(DIM / 128, MTOT / 128, 1);
    gemm_nt_kernel<<<gqkv, blk>>>(emb, Wq, bq, q, DIM, DIM, 1.0f, 0, 0, 0);
    gemm_nt_kernel<<<gqkv, blk>>>(emb, Wk, bk, k, DIM, DIM, 1.0f, 0, 0, 0);
    gemm_nt_kernel<<<gqkv, blk>>>(emb, Wv, bv, v, DIM, DIM, 1.0f, 0, 0, 0);

    // Scores: per-batch Q @ K^T * (1/sqrt(D))
    const dim3 gsc(SEQ / 128, SEQ / 128, BATCH);
    gemm_nt_kernel<<<gsc, blk>>>(q, k, nullptr, s, SEQ, DIM, SM_SCALE,
                                 (size_t)SEQ * DIM, (size_t)SEQ * DIM,
                                 (size_t)SEQ * SEQ);

    // Softmax rows (in place)
    softmax_kernel<<<MTOT, blk>>>(s);

    // Attended: per-batch P @ V
    const dim3 gpv(DIM / 128, SEQ / 128, BATCH);
    gemm_nn_kernel<<<gpv, blk>>>(s, v, att, DIM, SEQ,
                                 (size_t)SEQ * SEQ, (size_t)SEQ * DIM,
                                 (size_t)SEQ * DIM);

    // Residual + LayerNorm
    ln_kernel<<<MTOT, blk>>>(emb, att, gamma, beta, out);
}

// round 4
// speedup vs baseline: 1.7330x; 1.7330x over previous
#include <cuda_runtime.h>
#include <cuda_bf16.h>
#include <cstdint>
#include <math.h>

#define BATCH 4
#define SEQ   4096
#define DIM   1024
#define MTOT  (BATCH * SEQ)          // 16384
#define LN_EPS 1e-5f
#define SM_SCALE (1.0f / 32.0f)

// ---- GEMM tiling (mma.sync path, base sm_103 target: no tcgen05) ----------
#define TM 128
#define TN 128
#define KC 32                        // bf16 K per chunk
#define ROWB 80                      // padded smem row stride in bytes (40 halfwords)
#define OFF_AHI 0
#define OFF_ALO 10240                // 128 rows * 80 B
#define OFF_BHI 20480
#define OFF_BLO 30720
#define STAGE_BYTES 40960
#define GEMM_SMEM (2 * STAGE_BYTES)  // 81920

// ---------------------------------------------------------------------------
// Scratch (device globals: allocation-free rule)
// ---------------------------------------------------------------------------
__device__ __nv_bfloat16 g_emb_hi[(size_t)MTOT * DIM];
__device__ __nv_bfloat16 g_emb_lo[(size_t)MTOT * DIM];
__device__ __nv_bfloat16 g_w_hi[(size_t)3 * DIM * DIM];
__device__ __nv_bfloat16 g_w_lo[(size_t)3 * DIM * DIM];
__device__ __nv_bfloat16 g_q_hi[(size_t)MTOT * DIM];
__device__ __nv_bfloat16 g_q_lo[(size_t)MTOT * DIM];
__device__ __nv_bfloat16 g_k_hi[(size_t)MTOT * DIM];
__device__ __nv_bfloat16 g_k_lo[(size_t)MTOT * DIM];
__device__ __nv_bfloat16 g_v_hi[(size_t)MTOT * DIM];
__device__ __nv_bfloat16 g_v_lo[(size_t)MTOT * DIM];
__device__ __nv_bfloat16 g_vt_hi[(size_t)BATCH * DIM * SEQ];
__device__ __nv_bfloat16 g_vt_lo[(size_t)BATCH * DIM * SEQ];
__device__ float         g_s[(size_t)BATCH * SEQ * SEQ];
__device__ __nv_bfloat16 g_p_hi[(size_t)BATCH * SEQ * SEQ];
__device__ __nv_bfloat16 g_p_lo[(size_t)BATCH * SEQ * SEQ];
__device__ float         g_att[(size_t)MTOT * DIM];

// ---------------------------------------------------------------------------
// Helpers
// ---------------------------------------------------------------------------
__device__ __forceinline__ uint32_t smem_u32(const void* p) {
    uint32_t a;
    asm("{ .reg .u64 t; cvta.to.shared.u64 t, %1; cvt.u32.u64 %0, t; }"
        : "=r"(a) : "l"(p));
    return a;
}

__device__ __forceinline__ void cp16(uint32_t dst, const void* src) {
    size_t g = __cvta_generic_to_global(src);
    asm volatile("cp.async.cg.shared.global [%0], [%1], 16;" :: "r"(dst), "l"(g) : "memory");
}
__device__ __forceinline__ void cp_commit() {
    asm volatile("cp.async.commit_group;" ::: "memory");
}
template <int N> __device__ __forceinline__ void cp_wait() {
    asm volatile("cp.async.wait_group %0;" :: "n"(N) : "memory");
}

__device__ __forceinline__ void ldm4(uint32_t& r0, uint32_t& r1, uint32_t& r2, uint32_t& r3,
                                     uint32_t addr) {
    asm volatile("ldmatrix.sync.aligned.m8n8.x4.shared.b16 {%0,%1,%2,%3}, [%4];"
                 : "=r"(r0), "=r"(r1), "=r"(r2), "=r"(r3) : "r"(addr));
}

__device__ __forceinline__ void mma16816(float* d, const uint32_t* a, const uint32_t* b) {
    asm volatile(
        "mma.sync.aligned.m16n8k16.row.col.f32.bf16.bf16.f32 "
        "{%0,%1,%2,%3}, {%4,%5,%6,%7}, {%8,%9}, {%0,%1,%2,%3};"
        : "+f"(d[0]), "+f"(d[1]), "+f"(d[2]), "+f"(d[3])
        : "r"(a[0]), "r"(a[1]), "r"(a[2]), "r"(a[3]), "r"(b[0]), "r"(b[1]));
}

__device__ __forceinline__ void split2(float a, float b, uint32_t& h, uint32_t& l) {
    __nv_bfloat16 ha = __float2bfloat16(a), hb = __float2bfloat16(b);
    __nv_bfloat16 la = __float2bfloat16(a - __bfloat162float(ha));
    __nv_bfloat16 lb = __float2bfloat16(b - __bfloat162float(hb));
    h = (uint32_t)__bfloat16_as_ushort(ha) | ((uint32_t)__bfloat16_as_ushort(hb) << 16);
    l = (uint32_t)__bfloat16_as_ushort(la) | ((uint32_t)__bfloat16_as_ushort(lb) << 16);
}

// ---------------------------------------------------------------------------
// Split-3 bf16 mma.sync GEMM (NT): C[m,n] = alpha * sum_k A[m,k]*B[n,k] (+bias)
// A: [M,K] hi/lo bf16, B: [N,K] hi/lo bf16, K-major.
// Tile 128x128, chunk K=32, 256 threads (8 warps, warp tile 64x32).
// Output: fp32 C (if Cf) else bf16 hi/lo split pair.
// ---------------------------------------------------------------------------
__global__ void __launch_bounds__(256)
gemm_mma(const __nv_bfloat16* __restrict__ Ah_, const __nv_bfloat16* __restrict__ Al_,
         const __nv_bfloat16* __restrict__ Bh_, const __nv_bfloat16* __restrict__ Bl_,
         const float* __restrict__ bias,
         float* __restrict__ Cf,
         __nv_bfloat16* __restrict__ Chi, __nv_bfloat16* __restrict__ Clo,
         int N, int K, float alpha,
         size_t sA, size_t sB, size_t sC)
{
    extern __shared__ char smem[];
    const uint32_t sb = smem_u32(smem);
    const int tid = threadIdx.x, lane = tid & 31, wid = tid >> 5;
    const int warp_m = wid & 1;       // 0..1 (64 rows each)
    const int warp_n = wid >> 1;      // 0..3 (32 cols each)
    const int m0 = blockIdx.y * TM, n0 = blockIdx.x * TN;

    const __nv_bfloat16* Ah = Ah_ + blockIdx.z * sA;
    const __nv_bfloat16* Al = Al_ + blockIdx.z * sA;
    const __nv_bfloat16* Bh = Bh_ + blockIdx.z * sB;
    const __nv_bfloat16* Bl = Bl_ + blockIdx.z * sB;

    // gmem -> smem assignment: thread t loads row t/2, 32B half (t&1) of each tile
    const int lr = tid >> 1;
    const int lh = tid & 1;

    auto load_chunk = [&](int stage, int kc) {
        const uint32_t st = sb + stage * STAGE_BYTES;
        const uint32_t dofs = (uint32_t)lr * ROWB + lh * 32;
        {
            const size_t ao = (size_t)(m0 + lr) * K + (size_t)kc * KC + lh * 16;
            const char* pAh = (const char*)(Ah + ao);
            const char* pAl = (const char*)(Al + ao);
            cp16(st + OFF_AHI + dofs,      pAh);
            cp16(st + OFF_AHI + dofs + 16, pAh + 16);
            cp16(st + OFF_ALO + dofs,      pAl);
            cp16(st + OFF_ALO + dofs + 16, pAl + 16);
        }
        {
            const size_t bo = (size_t)(n0 + lr) * K + (size_t)kc * KC + lh * 16;
            const char* pBh = (const char*)(Bh + bo);
            const char* pBl = (const char*)(Bl + bo);
            cp16(st + OFF_BHI + dofs,      pBh);
            cp16(st + OFF_BHI + dofs + 16, pBh + 16);
            cp16(st + OFF_BLO + dofs,      pBl);
            cp16(st + OFF_BLO + dofs + 16, pBl + 16);
        }
        cp_commit();
    };

    // ldmatrix per-thread base offsets (bytes)
    // A (16x16 tile): lanes 0-15 rows 0..15 k-chunk0, lanes 16-31 rows 0..15 k-chunk+8
    const uint32_t aoff = (uint32_t)((warp_m * 64 + (lane & 15)) * ROWB + ((lane >> 4) & 1) * 16);
    // B (two n8 tiles): lanes 0-7 rows n..n+7 chunk0, 8-15 same rows chunk1,
    //                   16-23 rows n+8.. chunk0, 24-31 rows n+8.. chunk1
    const uint32_t boff = (uint32_t)((warp_n * 32 + ((lane >> 4) & 1) * 8 + (lane & 7)) * ROWB
                                     + ((lane >> 3) & 1) * 16);

    float acc[4][4][4];
#pragma unroll
    for (int mt = 0; mt < 4; ++mt)
#pragma unroll
        for (int nt = 0; nt < 4; ++nt)
#pragma unroll
            for (int r = 0; r < 4; ++r) acc[mt][nt][r] = 0.f;

    const int nk = K / KC;
    load_chunk(0, 0);

    for (int i = 0; i < nk; ++i) {
        const int cur = i & 1;
        if (i + 1 < nk) { load_chunk(cur ^ 1, i + 1); cp_wait<1>(); }
        else            { cp_wait<0>(); }
        __syncthreads();

        const uint32_t st    = sb + cur * STAGE_BYTES;
        const uint32_t abase = st + OFF_AHI + aoff;
        const uint32_t bbase = st + OFF_BHI + boff;

#pragma unroll
        for (int ks = 0; ks < 2; ++ks) {
            uint32_t bh[4][2], bl[4][2];
#pragma unroll
            for (int pr = 0; pr < 2; ++pr) {
                uint32_t r0, r1, r2, r3;
                ldm4(r0, r1, r2, r3, bbase + pr * 1280 + ks * 32);
                bh[pr*2][0] = r0; bh[pr*2][1] = r1; bh[pr*2+1][0] = r2; bh[pr*2+1][1] = r3;
                ldm4(r0, r1, r2, r3, bbase + 10240 + pr * 1280 + ks * 32);
                bl[pr*2][0] = r0; bl[pr*2][1] = r1; bl[pr*2+1][0] = r2; bl[pr*2+1][1] = r3;
            }
#pragma unroll
            for (int mt = 0; mt < 4; ++mt) {
                uint32_t ahf[4], alf[4];
                ldm4(ahf[0], ahf[1], ahf[2], ahf[3], abase + mt * 1280 + ks * 32);
                ldm4(alf[0], alf[1], alf[2], alf[3], abase + 10240 + mt * 1280 + ks * 32);
#pragma unroll
                for (int nt = 0; nt < 4; ++nt) {
                    mma16816(acc[mt][nt], ahf, bh[nt]);   // hi*hi
                    mma16816(acc[mt][nt], ahf, bl[nt]);   // hi*lo
                    mma16816(acc[mt][nt], alf, bh[nt]);   // lo*hi
                }
            }
        }
        __syncthreads();
    }

    // Epilogue: frag element (tr, c2): d0,d1 -> row tr, d2,d3 -> row tr+8
    const int tr = lane >> 2;
    const int c2 = (lane & 3) * 2;
#pragma unroll
    for (int mt = 0; mt < 4; ++mt) {
#pragma unroll
        for (int nt = 0; nt < 4; ++nt) {
            const int mrow = m0 + warp_m * 64 + mt * 16 + tr;
            const int ncol = n0 + warp_n * 32 + nt * 8 + c2;
            float x0 = acc[mt][nt][0] * alpha;
            float x1 = acc[mt][nt][1] * alpha;
            float x2 = acc[mt][nt][2] * alpha;
            float x3 = acc[mt][nt][3] * alpha;
            if (bias) {
                const float b0 = __ldg(bias + ncol), b1 = __ldg(bias + ncol + 1);
                x0 += b0; x1 += b1; x2 += b0; x3 += b1;
            }
            if (Cf) {
                float* c0 = Cf + blockIdx.z * sC + (size_t)mrow * N + ncol;
                *(float2*)c0                 = make_float2(x0, x1);
                *(float2*)(c0 + (size_t)8 * N) = make_float2(x2, x3);
            } else {
                __nv_bfloat16* h0 = Chi + blockIdx.z * sC + (size_t)mrow * N + ncol;
                __nv_bfloat16* l0 = Clo + blockIdx.z * sC + (size_t)mrow * N + ncol;
                uint32_t h, l;
                split2(x0, x1, h, l);
                *(uint32_t*)h0 = h; *(uint32_t*)l0 = l;
                split2(x2, x3, h, l);
                *(uint32_t*)(h0 + (size_t)8 * N) = h;
                *(uint32_t*)(l0 + (size_t)8 * N) = l;
            }
        }
    }
}

// ---------------------------------------------------------------------------
// fp32 -> bf16 hi/lo split (elementwise, 4 per thread)
// ---------------------------------------------------------------------------
__global__ void __launch_bounds__(256)
split_kernel(const float4* __restrict__ in, uint2* __restrict__ hi,
             uint2* __restrict__ lo, int n4)
{
    const int i = blockIdx.x * 256 + threadIdx.x;
    if (i >= n4) return;
    float4 x = in[i];
    uint2 H, L;
    split2(x.x, x.y, H.x, L.x);
    split2(x.z, x.w, H.y, L.y);
    hi[i] = H;
    lo[i] = L;
}

// ---------------------------------------------------------------------------
// Row softmax over SEQ (folds 1/sqrt(D)); emits bf16 hi/lo split of P.
// ---------------------------------------------------------------------------
__global__ void __launch_bounds__(256)
softmax_split_kernel(const float* __restrict__ S,
                     __nv_bfloat16* __restrict__ phi, __nv_bfloat16* __restrict__ plo)
{
    __shared__ float sh[8];
    const size_t rb = (size_t)blockIdx.x * SEQ;
    const float* p = S + rb;
    const int t = threadIdx.x, lane = t & 31, wrp = t >> 5;

    float4 v[4];
    float mx = -1e30f;
#pragma unroll
    for (int i = 0; i < 4; ++i) {
        v[i] = *(const float4*)(p + i * 1024 + t * 4);
        v[i].x *= SM_SCALE; v[i].y *= SM_SCALE; v[i].z *= SM_SCALE; v[i].w *= SM_SCALE;
        mx = fmaxf(mx, fmaxf(fmaxf(v[i].x, v[i].y), fmaxf(v[i].z, v[i].w)));
    }
#pragma unroll
    for (int o = 16; o > 0; o >>= 1) mx = fmaxf(mx, __shfl_xor_sync(0xffffffffu, mx, o));
    if (lane == 0) sh[wrp] = mx;
    __syncthreads();
    float m_all = sh[0];
#pragma unroll
    for (int w = 1; w < 8; ++w) m_all = fmaxf(m_all, sh[w]);
    __syncthreads();

    float sum = 0.f;
#pragma unroll
    for (int i = 0; i < 4; ++i) {
        v[i].x = __expf(v[i].x - m_all);
        v[i].y = __expf(v[i].y - m_all);
        v[i].z = __expf(v[i].z - m_all);
        v[i].w = __expf(v[i].w - m_all);
        sum += v[i].x + v[i].y + v[i].z + v[i].w;
    }
#pragma unroll
    for (int o = 16; o > 0; o >>= 1) sum += __shfl_xor_sync(0xffffffffu, sum, o);
    if (lane == 0) sh[wrp] = sum;
    __syncthreads();
    float s_all = 0.f;
#pragma unroll
    for (int w = 0; w < 8; ++w) s_all += sh[w];
    const float inv = 1.0f / s_all;

#pragma unroll
    for (int i = 0; i < 4; ++i) {
        const size_t e = rb + i * 1024 + t * 4;
        uint2 H, L;
        split2(v[i].x * inv, v[i].y * inv, H.x, L.x);
        split2(v[i].z * inv, v[i].w * inv, H.y, L.y);
        *(uint2*)(phi + e) = H;
        *(uint2*)(plo + e) = L;
    }
}

// ---------------------------------------------------------------------------
// bf16 transpose per batch: src [B][SEQ][DIM] -> dst [B][DIM][SEQ]
// ---------------------------------------------------------------------------
__global__ void __launch_bounds__(256)
transpose_kernel(const __nv_bfloat16* __restrict__ src, __nv_bfloat16* __restrict__ dst)
{
    __shared__ unsigned short tile[32][33];
    const int b = blockIdx.z;
    const int x  = blockIdx.x * 32 + threadIdx.x;   // dim
    const int y0 = blockIdx.y * 32;                 // seq
    const size_t sbase = (size_t)b * SEQ * DIM;
    const size_t dbase = (size_t)b * DIM * SEQ;
    const unsigned short* s = (const unsigned short*)src;
    unsigned short* d = (unsigned short*)dst;
#pragma unroll
    for (int j = 0; j < 32; j += 8)
        tile[threadIdx.y + j][threadIdx.x] =
            s[sbase + (size_t)(y0 + threadIdx.y + j) * DIM + x];
    __syncthreads();
    const int xo = blockIdx.y * 32 + threadIdx.x;   // seq
    const int yo = blockIdx.x * 32;                 // dim
#pragma unroll
    for (int j = 0; j < 32; j += 8)
        d[dbase + (size_t)(yo + threadIdx.y + j) * SEQ + xo] = tile[threadIdx.x][threadIdx.y + j];
}

// ---------------------------------------------------------------------------
// Residual + LayerNorm over D=1024.
// ---------------------------------------------------------------------------
__global__ void __launch_bounds__(256)
ln_kernel(const float* __restrict__ emb, const float* __restrict__ att,
          const float* __restrict__ gamma, const float* __restrict__ beta,
          float* __restrict__ out)
{
    __shared__ float shs[8];
    __shared__ float shq[8];
    const size_t base = (size_t)blockIdx.x * DIM;
    const int t = threadIdx.x, lane = t & 31, wrp = t >> 5;

    float4 e = *(const float4*)(emb + base + t * 4);
    float4 a = *(const float4*)(att + base + t * 4);
    float4 x;
    x.x = e.x + a.x; x.y = e.y + a.y; x.z = e.z + a.z; x.w = e.w + a.w;

    float s  = x.x + x.y + x.z + x.w;
    float sq = x.x*x.x + x.y*x.y + x.z*x.z + x.w*x.w;
#pragma unroll
    for (int o = 16; o > 0; o >>= 1) {
        s  += __shfl_xor_sync(0xffffffffu, s,  o);
        sq += __shfl_xor_sync(0xffffffffu, sq, o);
    }
    if (lane == 0) { shs[wrp] = s; shq[wrp] = sq; }
    __syncthreads();
    s = 0.f; sq = 0.f;
#pragma unroll
    for (int w = 0; w < 8; ++w) { s += shs[w]; sq += shq[w]; }

    const float mu   = s * (1.0f / (float)DIM);
    const float var  = sq * (1.0f / (float)DIM) - mu * mu;
    const float rstd = rsqrtf(var + LN_EPS);

    float4 g  = *(const float4*)(gamma + t * 4);
    float4 bt = *(const float4*)(beta  + t * 4);
    float4 r;
    r.x = g.x * (x.x - mu) * rstd + bt.x;
    r.y = g.y * (x.y - mu) * rstd + bt.y;
    r.z = g.z * (x.z - mu) * rstd + bt.z;
    r.w = g.w * (x.w - mu) * rstd + bt.w;
    *(float4*)(out + base + t * 4) = r;
}

// ---------------------------------------------------------------------------
// Launch
// ---------------------------------------------------------------------------
extern "C" void kernel_launch(void* const* d_in, const int* in_sizes, int n_in,
                              void* d_out, int out_size)
{
    (void)in_sizes; (void)n_in; (void)out_size;
    const float* emb   = (const float*)d_in[0];
    const float* Wq    = (const float*)d_in[4];
    const float* bq    = (const float*)d_in[5];
    const float* Wk    = (const float*)d_in[6];
    const float* bk    = (const float*)d_in[7];
    const float* Wv    = (const float*)d_in[8];
    const float* bv    = (const float*)d_in[9];
    const float* gamma = (const float*)d_in[10];
    const float* beta  = (const float*)d_in[11];
    float* out = (float*)d_out;

    void* p;
    __nv_bfloat16 *emb_hi, *emb_lo, *w_hi, *w_lo, *q_hi, *q_lo, *k_hi, *k_lo;
    __nv_bfloat16 *v_hi, *v_lo, *vt_hi, *vt_lo, *p_hi, *p_lo;
    float *s, *att;
    cudaGetSymbolAddress(&p, g_emb_hi); emb_hi = (__nv_bfloat16*)p;
    cudaGetSymbolAddress(&p, g_emb_lo); emb_lo = (__nv_bfloat16*)p;
    cudaGetSymbolAddress(&p, g_w_hi);   w_hi   = (__nv_bfloat16*)p;
    cudaGetSymbolAddress(&p, g_w_lo);   w_lo   = (__nv_bfloat16*)p;
    cudaGetSymbolAddress(&p, g_q_hi);   q_hi   = (__nv_bfloat16*)p;
    cudaGetSymbolAddress(&p, g_q_lo);   q_lo   = (__nv_bfloat16*)p;
    cudaGetSymbolAddress(&p, g_k_hi);   k_hi   = (__nv_bfloat16*)p;
    cudaGetSymbolAddress(&p, g_k_lo);   k_lo   = (__nv_bfloat16*)p;
    cudaGetSymbolAddress(&p, g_v_hi);   v_hi   = (__nv_bfloat16*)p;
    cudaGetSymbolAddress(&p, g_v_lo);   v_lo   = (__nv_bfloat16*)p;
    cudaGetSymbolAddress(&p, g_vt_hi);  vt_hi  = (__nv_bfloat16*)p;
    cudaGetSymbolAddress(&p, g_vt_lo);  vt_lo  = (__nv_bfloat16*)p;
    cudaGetSymbolAddress(&p, g_p_hi);   p_hi   = (__nv_bfloat16*)p;
    cudaGetSymbolAddress(&p, g_p_lo);   p_lo   = (__nv_bfloat16*)p;
    cudaGetSymbolAddress(&p, g_s);      s      = (float*)p;
    cudaGetSymbolAddress(&p, g_att);    att    = (float*)p;

    cudaFuncSetAttribute(gemm_mma, cudaFuncAttributeMaxDynamicSharedMemorySize, GEMM_SMEM);

    // Split inputs to bf16 hi/lo
    const int n4e = MTOT * DIM / 4;
    split_kernel<<<(n4e + 255) / 256, 256>>>((const float4*)emb, (uint2*)emb_hi, (uint2*)emb_lo, n4e);
    const int n4w = DIM * DIM / 4;
    split_kernel<<<(n4w + 255) / 256, 256>>>((const float4*)Wq, (uint2*)(w_hi),                 (uint2*)(w_lo),                 n4w);
    split_kernel<<<(n4w + 255) / 256, 256>>>((const float4*)Wk, (uint2*)(w_hi + DIM * DIM),     (uint2*)(w_lo + DIM * DIM),     n4w);
    split_kernel<<<(n4w + 255) / 256, 256>>>((const float4*)Wv, (uint2*)(w_hi + 2 * DIM * DIM), (uint2*)(w_lo + 2 * DIM * DIM), n4w);

    const dim3 blk(256);

    // QKV projections: [16384,1024] x [1024,1024]^T + bias -> bf16 hi/lo
    const dim3 gq(DIM / TN, MTOT / TM, 1);
    gemm_mma<<<gq, blk, GEMM_SMEM>>>(emb_hi, emb_lo, w_hi,                 w_lo,                 bq,
                                     nullptr, q_hi, q_lo, DIM, DIM, 1.f, 0, 0, 0);
    gemm_mma<<<gq, blk, GEMM_SMEM>>>(emb_hi, emb_lo, w_hi + DIM * DIM,     w_lo + DIM * DIM,     bk,
                                     nullptr, k_hi, k_lo, DIM, DIM, 1.f, 0, 0, 0);
    gemm_mma<<<gq, blk, GEMM_SMEM>>>(emb_hi, emb_lo, w_hi + 2 * DIM * DIM, w_lo + 2 * DIM * DIM, bv,
                                     nullptr, v_hi, v_lo, DIM, DIM, 1.f, 0, 0, 0);

    // Scores: per-batch Q @ K^T -> fp32 (scale folded into softmax)
    const dim3 gs(SEQ / TN, SEQ / TM, BATCH);
    gemm_mma<<<gs, blk, GEMM_SMEM>>>(q_hi, q_lo, k_hi, k_lo, nullptr,
                                     s, nullptr, nullptr, SEQ, DIM, 1.f,
                                     (size_t)SEQ * DIM, (size_t)SEQ * DIM, (size_t)SEQ * SEQ);

    // Softmax rows -> bf16 hi/lo P
    softmax_split_kernel<<<MTOT, 256>>>(s, p_hi, p_lo);

    // V transpose (hi and lo)
    const dim3 gt(DIM / 32, SEQ / 32, BATCH);
    transpose_kernel<<<gt, dim3(32, 8)>>>(v_hi, vt_hi);
    transpose_kernel<<<gt, dim3(32, 8)>>>(v_lo, vt_lo);

    // Attended: per-batch P @ V == P(hi/lo) @ Vt(hi/lo)^T -> fp32
    const dim3 gp(DIM / TN, SEQ / TM, BATCH);
    gemm_mma<<<gp, blk, GEMM_SMEM>>>(p_hi, p_lo, vt_hi, vt_lo, nullptr,
                                     att, nullptr, nullptr, DIM, SEQ, 1.f,
                                     (size_t)SEQ * SEQ, (size_t)DIM * SEQ, (size_t)SEQ * DIM);

    // Residual + LayerNorm
    ln_kernel<<<MTOT, 256>>>(emb, att, gamma, beta, out);
}

// round 5
// speedup vs baseline: 4.2078x; 2.4281x over previous
#include <cuda_runtime.h>
#include <cuda_bf16.h>
#include <cstdint>
#include <math.h>

#define BATCH 4
#define SEQ   4096
#define DIM   1024
#define MTOT  (BATCH * SEQ)          // 16384
#define LN_EPS 1e-5f
#define SM_SCALE (1.0f / 32.0f)

// ---- GEMM tiling (mma.sync bf16, single pass) -----------------------------
#define TM 128
#define TN 128
#define KC 32                        // bf16 K per chunk
#define ROWB 80                      // padded smem row stride in bytes
#define OFF_A 0
#define OFF_B 10240                  // 128 rows * 80 B
#define STAGE_BYTES 20480
#define GEMM_SMEM (2 * STAGE_BYTES)  // 40960

// ---------------------------------------------------------------------------
// Scratch (device globals: allocation-free rule)
// ---------------------------------------------------------------------------
__device__ __nv_bfloat16 g_emb_b[(size_t)MTOT * DIM];
__device__ __nv_bfloat16 g_w_b[(size_t)3 * DIM * DIM];
__device__ __nv_bfloat16 g_q_b[(size_t)MTOT * DIM];
__device__ __nv_bfloat16 g_k_b[(size_t)MTOT * DIM];
__device__ __nv_bfloat16 g_v_b[(size_t)MTOT * DIM];
__device__ __nv_bfloat16 g_vt_b[(size_t)BATCH * DIM * SEQ];
__device__ float         g_s[(size_t)BATCH * SEQ * SEQ];
__device__ __nv_bfloat16 g_p_b[(size_t)BATCH * SEQ * SEQ];
__device__ float         g_att[(size_t)MTOT * DIM];

// ---------------------------------------------------------------------------
// Helpers
// ---------------------------------------------------------------------------
__device__ __forceinline__ uint32_t smem_u32(const void* p) {
    uint32_t a;
    asm("{ .reg .u64 t; cvta.to.shared.u64 t, %1; cvt.u32.u64 %0, t; }"
        : "=r"(a) : "l"(p));
    return a;
}

__device__ __forceinline__ void cp16(uint32_t dst, const void* src) {
    size_t g = __cvta_generic_to_global(src);
    asm volatile("cp.async.cg.shared.global [%0], [%1], 16;" :: "r"(dst), "l"(g) : "memory");
}
__device__ __forceinline__ void cp_commit() {
    asm volatile("cp.async.commit_group;" ::: "memory");
}
template <int N> __device__ __forceinline__ void cp_wait() {
    asm volatile("cp.async.wait_group %0;" :: "n"(N) : "memory");
}

__device__ __forceinline__ void ldm4(uint32_t& r0, uint32_t& r1, uint32_t& r2, uint32_t& r3,
                                     uint32_t addr) {
    asm volatile("ldmatrix.sync.aligned.m8n8.x4.shared.b16 {%0,%1,%2,%3}, [%4];"
                 : "=r"(r0), "=r"(r1), "=r"(r2), "=r"(r3) : "r"(addr));
}

__device__ __forceinline__ void mma16816(float* d, const uint32_t* a, const uint32_t* b) {
    asm volatile(
        "mma.sync.aligned.m16n8k16.row.col.f32.bf16.bf16.f32 "
        "{%0,%1,%2,%3}, {%4,%5,%6,%7}, {%8,%9}, {%0,%1,%2,%3};"
        : "+f"(d[0]), "+f"(d[1]), "+f"(d[2]), "+f"(d[3])
        : "r"(a[0]), "r"(a[1]), "r"(a[2]), "r"(a[3]), "r"(b[0]), "r"(b[1]));
}

__device__ __forceinline__ uint32_t pack_bf2(float a, float b) {
    __nv_bfloat162 v = __floats2bfloat162_rn(a, b);
    return *(uint32_t*)&v;
}

// ---------------------------------------------------------------------------
// bf16 mma.sync GEMM (NT): C[m,n] = alpha * sum_k A[m,k]*B[n,k] (+bias)
// A: [M,K] bf16, B: [N,K] bf16, K-major. Tile 128x128, chunk K=32,
// 256 threads (8 warps, warp tile 64x32). Output fp32 (Cf) or bf16 (Cb).
// ---------------------------------------------------------------------------
__global__ void __launch_bounds__(256, 2)
gemm_mma(const __nv_bfloat16* __restrict__ A_, const __nv_bfloat16* __restrict__ B_,
         const float* __restrict__ bias,
         float* __restrict__ Cf, __nv_bfloat16* __restrict__ Cb,
         int N, int K, float alpha,
         size_t sA, size_t sB, size_t sC)
{
    extern __shared__ char smem[];
    const uint32_t sb = smem_u32(smem);
    const int tid = threadIdx.x, lane = tid & 31, wid = tid >> 5;
    const int warp_m = wid & 1;       // 0..1 (64 rows each)
    const int warp_n = wid >> 1;      // 0..3 (32 cols each)
    const int m0 = blockIdx.y * TM, n0 = blockIdx.x * TN;

    const __nv_bfloat16* A = A_ + blockIdx.z * sA;
    const __nv_bfloat16* B = B_ + blockIdx.z * sB;

    // gmem -> smem: thread t loads row t/2, 32B half (t&1)
    const int lr = tid >> 1;
    const int lh = tid & 1;

    auto load_chunk = [&](int stage, int kc) {
        const uint32_t st = sb + stage * STAGE_BYTES;
        const uint32_t dofs = (uint32_t)lr * ROWB + lh * 32;
        const size_t ao = (size_t)(m0 + lr) * K + (size_t)kc * KC + lh * 16;
        const char* pA = (const char*)(A + ao);
        cp16(st + OFF_A + dofs,      pA);
        cp16(st + OFF_A + dofs + 16, pA + 16);
        const size_t bo = (size_t)(n0 + lr) * K + (size_t)kc * KC + lh * 16;
        const char* pB = (const char*)(B + bo);
        cp16(st + OFF_B + dofs,      pB);
        cp16(st + OFF_B + dofs + 16, pB + 16);
        cp_commit();
    };

    // ldmatrix per-thread base offsets (bytes)
    const uint32_t aoff = (uint32_t)((warp_m * 64 + (lane & 15)) * ROWB + ((lane >> 4) & 1) * 16);
    const uint32_t boff = (uint32_t)((warp_n * 32 + ((lane >> 4) & 1) * 8 + (lane & 7)) * ROWB
                                     + ((lane >> 3) & 1) * 16);

    float acc[4][4][4];
#pragma unroll
    for (int mt = 0; mt < 4; ++mt)
#pragma unroll
        for (int nt = 0; nt < 4; ++nt)
#pragma unroll
            for (int r = 0; r < 4; ++r) acc[mt][nt][r] = 0.f;

    const int nk = K / KC;
    load_chunk(0, 0);

    for (int i = 0; i < nk; ++i) {
        const int cur = i & 1;
        if (i + 1 < nk) { load_chunk(cur ^ 1, i + 1); cp_wait<1>(); }
        else            { cp_wait<0>(); }
        __syncthreads();

        const uint32_t st    = sb + cur * STAGE_BYTES;
        const uint32_t abase = st + OFF_A + aoff;
        const uint32_t bbase = st + OFF_B + boff;

#pragma unroll
        for (int ks = 0; ks < 2; ++ks) {
            uint32_t bf[4][2];
#pragma unroll
            for (int pr = 0; pr < 2; ++pr) {
                uint32_t r0, r1, r2, r3;
                ldm4(r0, r1, r2, r3, bbase + pr * 1280 + ks * 32);
                bf[pr*2][0] = r0; bf[pr*2][1] = r1; bf[pr*2+1][0] = r2; bf[pr*2+1][1] = r3;
            }
#pragma unroll
            for (int mt = 0; mt < 4; ++mt) {
                uint32_t af[4];
                ldm4(af[0], af[1], af[2], af[3], abase + mt * 1280 + ks * 32);
#pragma unroll
                for (int nt = 0; nt < 4; ++nt)
                    mma16816(acc[mt][nt], af, bf[nt]);
            }
        }
        __syncthreads();
    }

    // Epilogue: frag (tr, c2): d0,d1 -> row tr, d2,d3 -> row tr+8
    const int tr = lane >> 2;
    const int c2 = (lane & 3) * 2;
#pragma unroll
    for (int mt = 0; mt < 4; ++mt) {
#pragma unroll
        for (int nt = 0; nt < 4; ++nt) {
            const int mrow = m0 + warp_m * 64 + mt * 16 + tr;
            const int ncol = n0 + warp_n * 32 + nt * 8 + c2;
            float x0 = acc[mt][nt][0] * alpha;
            float x1 = acc[mt][nt][1] * alpha;
            float x2 = acc[mt][nt][2] * alpha;
            float x3 = acc[mt][nt][3] * alpha;
            if (bias) {
                const float b0 = __ldg(bias + ncol), b1 = __ldg(bias + ncol + 1);
                x0 += b0; x1 += b1; x2 += b0; x3 += b1;
            }
            if (Cf) {
                float* c0 = Cf + blockIdx.z * sC + (size_t)mrow * N + ncol;
                *(float2*)c0                   = make_float2(x0, x1);
                *(float2*)(c0 + (size_t)8 * N) = make_float2(x2, x3);
            } else {
                __nv_bfloat16* c0 = Cb + blockIdx.z * sC + (size_t)mrow * N + ncol;
                *(uint32_t*)c0                   = pack_bf2(x0, x1);
                *(uint32_t*)(c0 + (size_t)8 * N) = pack_bf2(x2, x3);
            }
        }
    }
}

// ---------------------------------------------------------------------------
// fp32 -> bf16 convert (4 per thread)
// ---------------------------------------------------------------------------
__global__ void __launch_bounds__(256)
cvt_kernel(const float4* __restrict__ in, uint2* __restrict__ out, int n4)
{
    const int i = blockIdx.x * 256 + threadIdx.x;
    if (i >= n4) return;
    float4 x = in[i];
    uint2 o;
    o.x = pack_bf2(x.x, x.y);
    o.y = pack_bf2(x.z, x.w);
    out[i] = o;
}

// ---------------------------------------------------------------------------
// Row softmax over SEQ (folds 1/sqrt(D)); emits bf16 P.
// ---------------------------------------------------------------------------
__global__ void __launch_bounds__(256)
softmax_kernel(const float* __restrict__ S, __nv_bfloat16* __restrict__ P)
{
    __shared__ float sh[8];
    const size_t rb = (size_t)blockIdx.x * SEQ;
    const float* p = S + rb;
    const int t = threadIdx.x, lane = t & 31, wrp = t >> 5;

    float4 v[4];
    float mx = -1e30f;
#pragma unroll
    for (int i = 0; i < 4; ++i) {
        v[i] = *(const float4*)(p + i * 1024 + t * 4);
        v[i].x *= SM_SCALE; v[i].y *= SM_SCALE; v[i].z *= SM_SCALE; v[i].w *= SM_SCALE;
        mx = fmaxf(mx, fmaxf(fmaxf(v[i].x, v[i].y), fmaxf(v[i].z, v[i].w)));
    }
#pragma unroll
    for (int o = 16; o > 0; o >>= 1) mx = fmaxf(mx, __shfl_xor_sync(0xffffffffu, mx, o));
    if (lane == 0) sh[wrp] = mx;
    __syncthreads();
    float m_all = sh[0];
#pragma unroll
    for (int w = 1; w < 8; ++w) m_all = fmaxf(m_all, sh[w]);
    __syncthreads();

    float sum = 0.f;
#pragma unroll
    for (int i = 0; i < 4; ++i) {
        v[i].x = __expf(v[i].x - m_all);
        v[i].y = __expf(v[i].y - m_all);
        v[i].z = __expf(v[i].z - m_all);
        v[i].w = __expf(v[i].w - m_all);
        sum += v[i].x + v[i].y + v[i].z + v[i].w;
    }
#pragma unroll
    for (int o = 16; o > 0; o >>= 1) sum += __shfl_xor_sync(0xffffffffu, sum, o);
    if (lane == 0) sh[wrp] = sum;
    __syncthreads();
    float s_all = 0.f;
#pragma unroll
    for (int w = 0; w < 8; ++w) s_all += sh[w];
    const float inv = 1.0f / s_all;

#pragma unroll
    for (int i = 0; i < 4; ++i) {
        const size_t e = rb + i * 1024 + t * 4;
        uint2 o;
        o.x = pack_bf2(v[i].x * inv, v[i].y * inv);
        o.y = pack_bf2(v[i].z * inv, v[i].w * inv);
        *(uint2*)(P + e) = o;
    }
}

// ---------------------------------------------------------------------------
// bf16 transpose per batch: src [B][SEQ][DIM] -> dst [B][DIM][SEQ]
// ---------------------------------------------------------------------------
__global__ void __launch_bounds__(256)
transpose_kernel(const __nv_bfloat16* __restrict__ src, __nv_bfloat16* __restrict__ dst)
{
    __shared__ unsigned short tile[32][33];
    const int b = blockIdx.z;
    const int x  = blockIdx.x * 32 + threadIdx.x;   // dim
    const int y0 = blockIdx.y * 32;                 // seq
    const size_t sbase = (size_t)b * SEQ * DIM;
    const size_t dbase = (size_t)b * DIM * SEQ;
    const unsigned short* s = (const unsigned short*)src;
    unsigned short* d = (unsigned short*)dst;
#pragma unroll
    for (int j = 0; j < 32; j += 8)
        tile[threadIdx.y + j][threadIdx.x] =
            s[sbase + (size_t)(y0 + threadIdx.y + j) * DIM + x];
    __syncthreads();
    const int xo = blockIdx.y * 32 + threadIdx.x;   // seq
    const int yo = blockIdx.x * 32;                 // dim
#pragma unroll
    for (int j = 0; j < 32; j += 8)
        d[dbase + (size_t)(yo + threadIdx.y + j) * SEQ + xo] = tile[threadIdx.x][threadIdx.y + j];
}

// ---------------------------------------------------------------------------
// Residual + LayerNorm over D=1024.
// ---------------------------------------------------------------------------
__global__ void __launch_bounds__(256)
ln_kernel(const float* __restrict__ emb, const float* __restrict__ att,
          const float* __restrict__ gamma, const float* __restrict__ beta,
          float* __restrict__ out)
{
    __shared__ float shs[8];
    __shared__ float shq[8];
    const size_t base = (size_t)blockIdx.x * DIM;
    const int t = threadIdx.x, lane = t & 31, wrp = t >> 5;

    float4 e = *(const float4*)(emb + base + t * 4);
    float4 a = *(const float4*)(att + base + t * 4);
    float4 x;
    x.x = e.x + a.x; x.y = e.y + a.y; x.z = e.z + a.z; x.w = e.w + a.w;

    float s  = x.x + x.y + x.z + x.w;
    float sq = x.x*x.x + x.y*x.y + x.z*x.z + x.w*x.w;
#pragma unroll
    for (int o = 16; o > 0; o >>= 1) {
        s  += __shfl_xor_sync(0xffffffffu, s,  o);
        sq += __shfl_xor_sync(0xffffffffu, sq, o);
    }
    if (lane == 0) { shs[wrp] = s; shq[wrp] = sq; }
    __syncthreads();
    s = 0.f; sq = 0.f;
#pragma unroll
    for (int w = 0; w < 8; ++w) { s += shs[w]; sq += shq[w]; }

    const float mu   = s * (1.0f / (float)DIM);
    const float var  = sq * (1.0f / (float)DIM) - mu * mu;
    const float rstd = rsqrtf(var + LN_EPS);

    float4 g  = *(const float4*)(gamma + t * 4);
    float4 bt = *(const float4*)(beta  + t * 4);
    float4 r;
    r.x = g.x * (x.x - mu) * rstd + bt.x;
    r.y = g.y * (x.y - mu) * rstd + bt.y;
    r.z = g.z * (x.z - mu) * rstd + bt.z;
    r.w = g.w * (x.w - mu) * rstd + bt.w;
    *(float4*)(out + base + t * 4) = r;
}

// ---------------------------------------------------------------------------
// Launch
// ---------------------------------------------------------------------------
extern "C" void kernel_launch(void* const* d_in, const int* in_sizes, int n_in,
                              void* d_out, int out_size)
{
    (void)in_sizes; (void)n_in; (void)out_size;
    const float* emb   = (const float*)d_in[0];
    const float* Wq    = (const float*)d_in[4];
    const float* bq    = (const float*)d_in[5];
    const float* Wk    = (const float*)d_in[6];
    const float* bk    = (const float*)d_in[7];
    const float* Wv    = (const float*)d_in[8];
    const float* bv    = (const float*)d_in[9];
    const float* gamma = (const float*)d_in[10];
    const float* beta  = (const float*)d_in[11];
    float* out = (float*)d_out;

    void* p;
    __nv_bfloat16 *emb_b, *w_b, *q_b, *k_b, *v_b, *vt_b, *p_b;
    float *s, *att;
    cudaGetSymbolAddress(&p, g_emb_b); emb_b = (__nv_bfloat16*)p;
    cudaGetSymbolAddress(&p, g_w_b);   w_b   = (__nv_bfloat16*)p;
    cudaGetSymbolAddress(&p, g_q_b);   q_b   = (__nv_bfloat16*)p;
    cudaGetSymbolAddress(&p, g_k_b);   k_b   = (__nv_bfloat16*)p;
    cudaGetSymbolAddress(&p, g_v_b);   v_b   = (__nv_bfloat16*)p;
    cudaGetSymbolAddress(&p, g_vt_b);  vt_b  = (__nv_bfloat16*)p;
    cudaGetSymbolAddress(&p, g_p_b);   p_b   = (__nv_bfloat16*)p;
    cudaGetSymbolAddress(&p, g_s);     s     = (float*)p;
    cudaGetSymbolAddress(&p, g_att);   att   = (float*)p;

    cudaFuncSetAttribute(gemm_mma, cudaFuncAttributeMaxDynamicSharedMemorySize, GEMM_SMEM);

    // Convert inputs to bf16
    const int n4e = MTOT * DIM / 4;
    cvt_kernel<<<(n4e + 255) / 256, 256>>>((const float4*)emb, (uint2*)emb_b, n4e);
    const int n4w = DIM * DIM / 4;
    cvt_kernel<<<(n4w + 255) / 256, 256>>>((const float4*)Wq, (uint2*)(w_b),                 n4w);
    cvt_kernel<<<(n4w + 255) / 256, 256>>>((const float4*)Wk, (uint2*)(w_b + DIM * DIM),     n4w);
    cvt_kernel<<<(n4w + 255) / 256, 256>>>((const float4*)Wv, (uint2*)(w_b + 2 * DIM * DIM), n4w);

    const dim3 blk(256);

    // QKV projections: [16384,1024] x [1024,1024]^T + bias -> bf16
    const dim3 gq(DIM / TN, MTOT / TM, 1);
    gemm_mma<<<gq, blk, GEMM_SMEM>>>(emb_b, w_b,                 bq, nullptr, q_b, DIM, DIM, 1.f, 0, 0, 0);
    gemm_mma<<<gq, blk, GEMM_SMEM>>>(emb_b, w_b + DIM * DIM,     bk, nullptr, k_b, DIM, DIM, 1.f, 0, 0, 0);
    gemm_mma<<<gq, blk, GEMM_SMEM>>>(emb_b, w_b + 2 * DIM * DIM, bv, nullptr, v_b, DIM, DIM, 1.f, 0, 0, 0);

    // Scores: per-batch Q @ K^T -> fp32 (scale folded into softmax)
    const dim3 gs(SEQ / TN, SEQ / TM, BATCH);
    gemm_mma<<<gs, blk, GEMM_SMEM>>>(q_b, k_b, nullptr, s, nullptr, SEQ, DIM, 1.f,
                                     (size_t)SEQ * DIM, (size_t)SEQ * DIM, (size_t)SEQ * SEQ);

    // Softmax rows -> bf16 P
    softmax_kernel<<<MTOT, 256>>>(s, p_b);

    // V transpose
    const dim3 gt(DIM / 32, SEQ / 32, BATCH);
    transpose_kernel<<<gt, dim3(32, 8)>>>(v_b, vt_b);

    // Attended: per-batch P @ V == P @ Vt^T -> fp32
    const dim3 gp(DIM / TN, SEQ / TM, BATCH);
    gemm_mma<<<gp, blk, GEMM_SMEM>>>(p_b, vt_b, nullptr, att, nullptr, DIM, SEQ, 1.f,
                                     (size_t)SEQ * SEQ, (size_t)DIM * SEQ, (size_t)SEQ * DIM);

    // Residual + LayerNorm
    ln_kernel<<<MTOT, 256>>>(emb, att, gamma, beta, out);
}

// round 6
// speedup vs baseline: 4.7995x; 1.1406x over previous
#include <cuda_runtime.h>
#include <cuda_bf16.h>
#include <cstdint>
#include <math.h>

#define BATCH 4
#define SEQ   4096
#define DIM   1024
#define MTOT  (BATCH * SEQ)          // 16384
#define LN_EPS 1e-5f
#define SM_SCALE (1.0f / 32.0f)

// ---- GEMM tiling (mma.sync bf16, 3-stage pipeline) ------------------------
#define TM 128
#define TN 128
#define KC 32                        // bf16 K per chunk
#define ROWB 80                      // padded smem row stride in bytes
#define OFF_A 0
#define OFF_B 10240                  // 128 rows * 80 B
#define STAGE_BYTES 20480
#define NSTAGE 3
#define GEMM_SMEM (NSTAGE * STAGE_BYTES)   // 61440

// ---------------------------------------------------------------------------
// Scratch (device globals: allocation-free rule)
// ---------------------------------------------------------------------------
__device__ __nv_bfloat16 g_emb_b[(size_t)MTOT * DIM];
__device__ __nv_bfloat16 g_w_b[(size_t)3 * DIM * DIM];
__device__ __nv_bfloat16 g_q_b[(size_t)MTOT * DIM];
__device__ __nv_bfloat16 g_k_b[(size_t)MTOT * DIM];
__device__ __nv_bfloat16 g_vt_b[(size_t)DIM * MTOT];        // [1024][16384] = V^T per batch slices
__device__ __nv_bfloat16 g_s_b[(size_t)BATCH * SEQ * SEQ];  // scores bf16
__device__ __nv_bfloat16 g_p_b[(size_t)BATCH * SEQ * SEQ];  // probs bf16
__device__ float         g_att[(size_t)MTOT * DIM];

// ---------------------------------------------------------------------------
// Helpers
// ---------------------------------------------------------------------------
__device__ __forceinline__ uint32_t smem_u32(const void* p) {
    uint32_t a;
    asm("{ .reg .u64 t; cvta.to.shared.u64 t, %1; cvt.u32.u64 %0, t; }"
        : "=r"(a) : "l"(p));
    return a;
}

__device__ __forceinline__ void cp16(uint32_t dst, const void* src) {
    size_t g = __cvta_generic_to_global(src);
    asm volatile("cp.async.cg.shared.global [%0], [%1], 16;" :: "r"(dst), "l"(g) : "memory");
}
__device__ __forceinline__ void cp_commit() {
    asm volatile("cp.async.commit_group;" ::: "memory");
}
template <int N> __device__ __forceinline__ void cp_wait() {
    asm volatile("cp.async.wait_group %0;" :: "n"(N) : "memory");
}

__device__ __forceinline__ void ldm4(uint32_t& r0, uint32_t& r1, uint32_t& r2, uint32_t& r3,
                                     uint32_t addr) {
    asm volatile("ldmatrix.sync.aligned.m8n8.x4.shared.b16 {%0,%1,%2,%3}, [%4];"
                 : "=r"(r0), "=r"(r1), "=r"(r2), "=r"(r3) : "r"(addr));
}

__device__ __forceinline__ void mma16816(float* d, const uint32_t* a, const uint32_t* b) {
    asm volatile(
        "mma.sync.aligned.m16n8k16.row.col.f32.bf16.bf16.f32 "
        "{%0,%1,%2,%3}, {%4,%5,%6,%7}, {%8,%9}, {%0,%1,%2,%3};"
        : "+f"(d[0]), "+f"(d[1]), "+f"(d[2]), "+f"(d[3])
        : "r"(a[0]), "r"(a[1]), "r"(a[2]), "r"(a[3]), "r"(b[0]), "r"(b[1]));
}

__device__ __forceinline__ uint32_t pack_bf2(float a, float b) {
    __nv_bfloat162 v = __floats2bfloat162_rn(a, b);
    return *(uint32_t*)&v;
}

// ---------------------------------------------------------------------------
// bf16 mma.sync GEMM (NT): C[m,n] = alpha * sum_k A[m,k]*B[n,k] (+bias)
// A: [M,K] row stride K; B: rows indexed by n, row stride ldB.
// Tile 128x128, chunk K=32, 3-stage cp.async pipeline, 256 threads (8 warps).
// Output fp32 (Cf) or bf16 (Cb). bias_row: bias indexed by m instead of n.
// ---------------------------------------------------------------------------
__global__ void __launch_bounds__(256, 2)
gemm_mma(const __nv_bfloat16* __restrict__ A_, const __nv_bfloat16* __restrict__ B_,
         const float* __restrict__ bias, int bias_row,
         float* __restrict__ Cf, __nv_bfloat16* __restrict__ Cb,
         int N, int K, int ldB, float alpha,
         size_t sA, size_t sB, size_t sC)
{
    extern __shared__ char smem[];
    const uint32_t sb = smem_u32(smem);
    const int tid = threadIdx.x, lane = tid & 31, wid = tid >> 5;
    const int warp_m = wid & 1;       // 0..1 (64 rows each)
    const int warp_n = wid >> 1;      // 0..3 (32 cols each)
    const int m0 = blockIdx.y * TM, n0 = blockIdx.x * TN;

    const __nv_bfloat16* A = A_ + blockIdx.z * sA;
    const __nv_bfloat16* B = B_ + blockIdx.z * sB;

    // gmem -> smem: thread t loads row t/2, 32B half (t&1)
    const int lr = tid >> 1;
    const int lh = tid & 1;

    auto load_chunk = [&](int stage, int kc) {
        const uint32_t st = sb + stage * STAGE_BYTES;
        const uint32_t dofs = (uint32_t)lr * ROWB + lh * 32;
        const size_t ao = (size_t)(m0 + lr) * K + (size_t)kc * KC + lh * 16;
        const char* pA = (const char*)(A + ao);
        cp16(st + OFF_A + dofs,      pA);
        cp16(st + OFF_A + dofs + 16, pA + 16);
        const size_t bo = (size_t)(n0 + lr) * ldB + (size_t)kc * KC + lh * 16;
        const char* pB = (const char*)(B + bo);
        cp16(st + OFF_B + dofs,      pB);
        cp16(st + OFF_B + dofs + 16, pB + 16);
        cp_commit();
    };

    // ldmatrix per-thread base offsets (bytes)
    const uint32_t aoff = (uint32_t)((warp_m * 64 + (lane & 15)) * ROWB + ((lane >> 4) & 1) * 16);
    const uint32_t boff = (uint32_t)((warp_n * 32 + ((lane >> 4) & 1) * 8 + (lane & 7)) * ROWB
                                     + ((lane >> 3) & 1) * 16);

    float acc[4][4][4];
#pragma unroll
    for (int mt = 0; mt < 4; ++mt)
#pragma unroll
        for (int nt = 0; nt < 4; ++nt)
#pragma unroll
            for (int r = 0; r < 4; ++r) acc[mt][nt][r] = 0.f;

    const int nk = K / KC;
    load_chunk(0, 0);
    load_chunk(1, 1);

    for (int i = 0; i < nk; ++i) {
        const int cur = i % NSTAGE;
        cp_wait<1>();              // chunk i resident
        __syncthreads();           // all warps done with chunk i-1; chunk i visible
        if (i + 2 < nk) load_chunk((i + 2) % NSTAGE, i + 2);
        else            cp_commit();

        const uint32_t st    = sb + cur * STAGE_BYTES;
        const uint32_t abase = st + OFF_A + aoff;
        const uint32_t bbase = st + OFF_B + boff;

#pragma unroll
        for (int ks = 0; ks < 2; ++ks) {
            uint32_t bf[4][2];
#pragma unroll
            for (int pr = 0; pr < 2; ++pr) {
                uint32_t r0, r1, r2, r3;
                ldm4(r0, r1, r2, r3, bbase + pr * 1280 + ks * 32);
                bf[pr*2][0] = r0; bf[pr*2][1] = r1; bf[pr*2+1][0] = r2; bf[pr*2+1][1] = r3;
            }
#pragma unroll
            for (int mt = 0; mt < 4; ++mt) {
                uint32_t af[4];
                ldm4(af[0], af[1], af[2], af[3], abase + mt * 1280 + ks * 32);
#pragma unroll
                for (int nt = 0; nt < 4; ++nt)
                    mma16816(acc[mt][nt], af, bf[nt]);
            }
        }
    }

    // Epilogue: frag (tr, c2): d0,d1 -> row tr, d2,d3 -> row tr+8
    const int tr = lane >> 2;
    const int c2 = (lane & 3) * 2;
#pragma unroll
    for (int mt = 0; mt < 4; ++mt) {
#pragma unroll
        for (int nt = 0; nt < 4; ++nt) {
            const int mrow = m0 + warp_m * 64 + mt * 16 + tr;
            const int ncol = n0 + warp_n * 32 + nt * 8 + c2;
            float x0 = acc[mt][nt][0] * alpha;
            float x1 = acc[mt][nt][1] * alpha;
            float x2 = acc[mt][nt][2] * alpha;
            float x3 = acc[mt][nt][3] * alpha;
            if (bias) {
                if (bias_row) {
                    const float b0 = __ldg(bias + mrow), b1 = __ldg(bias + mrow + 8);
                    x0 += b0; x1 += b0; x2 += b1; x3 += b1;
                } else {
                    const float b0 = __ldg(bias + ncol), b1 = __ldg(bias + ncol + 1);
                    x0 += b0; x1 += b1; x2 += b0; x3 += b1;
                }
            }
            if (Cf) {
                float* c0 = Cf + blockIdx.z * sC + (size_t)mrow * N + ncol;
                *(float2*)c0                   = make_float2(x0, x1);
                *(float2*)(c0 + (size_t)8 * N) = make_float2(x2, x3);
            } else {
                __nv_bfloat16* c0 = Cb + blockIdx.z * sC + (size_t)mrow * N + ncol;
                *(uint32_t*)c0                   = pack_bf2(x0, x1);
                *(uint32_t*)(c0 + (size_t)8 * N) = pack_bf2(x2, x3);
            }
        }
    }
}

// ---------------------------------------------------------------------------
// fp32 -> bf16 convert (4 per thread)
// ---------------------------------------------------------------------------
__global__ void __launch_bounds__(256)
cvt_kernel(const float4* __restrict__ in, uint2* __restrict__ out, int n4)
{
    const int i = blockIdx.x * 256 + threadIdx.x;
    if (i >= n4) return;
    float4 x = in[i];
    uint2 o;
    o.x = pack_bf2(x.x, x.y);
    o.y = pack_bf2(x.z, x.w);
    out[i] = o;
}

// ---------------------------------------------------------------------------
// Row softmax over SEQ from bf16 scores (folds 1/sqrt(D)); emits bf16 P.
// 256 threads, 16 elems/thread.
// ---------------------------------------------------------------------------
__global__ void __launch_bounds__(256)
softmax_kernel(const __nv_bfloat16* __restrict__ S, __nv_bfloat16* __restrict__ P)
{
    __shared__ float sh[8];
    const size_t rb = (size_t)blockIdx.x * SEQ;
    const int t = threadIdx.x, lane = t & 31, wrp = t >> 5;

    // Load 16 bf16 per thread as 2 x uint4 (two 2048-element halves)
    uint4 u0 = *(const uint4*)(S + rb + t * 8);
    uint4 u1 = *(const uint4*)(S + rb + 2048 + t * 8);

    float f[16];
    {
        const uint32_t* w0 = (const uint32_t*)&u0;
        const uint32_t* w1 = (const uint32_t*)&u1;
#pragma unroll
        for (int j = 0; j < 4; ++j) {
            float2 a = __bfloat1622float2(*(const __nv_bfloat162*)&w0[j]);
            f[j*2]   = a.x; f[j*2+1] = a.y;
            float2 b = __bfloat1622float2(*(const __nv_bfloat162*)&w1[j]);
            f[8+j*2] = b.x; f[8+j*2+1] = b.y;
        }
    }

    float mx = -1e30f;
#pragma unroll
    for (int j = 0; j < 16; ++j) mx = fmaxf(mx, f[j]);
#pragma unroll
    for (int o = 16; o > 0; o >>= 1) mx = fmaxf(mx, __shfl_xor_sync(0xffffffffu, mx, o));
    if (lane == 0) sh[wrp] = mx;
    __syncthreads();
    float m_all = sh[0];
#pragma unroll
    for (int w = 1; w < 8; ++w) m_all = fmaxf(m_all, sh[w]);
    __syncthreads();

    float sum = 0.f;
#pragma unroll
    for (int j = 0; j < 16; ++j) {
        f[j] = __expf((f[j] - m_all) * SM_SCALE);
        sum += f[j];
    }
#pragma unroll
    for (int o = 16; o > 0; o >>= 1) sum += __shfl_xor_sync(0xffffffffu, sum, o);
    if (lane == 0) sh[wrp] = sum;
    __syncthreads();
    float s_all = 0.f;
#pragma unroll
    for (int w = 0; w < 8; ++w) s_all += sh[w];
    const float inv = 1.0f / s_all;

    uint4 o0, o1;
    uint32_t* w0 = (uint32_t*)&o0;
    uint32_t* w1 = (uint32_t*)&o1;
#pragma unroll
    for (int j = 0; j < 4; ++j) {
        w0[j] = pack_bf2(f[j*2] * inv,   f[j*2+1] * inv);
        w1[j] = pack_bf2(f[8+j*2] * inv, f[8+j*2+1] * inv);
    }
    *(uint4*)(P + rb + t * 8)        = o0;
    *(uint4*)(P + rb + 2048 + t * 8) = o1;
}

// ---------------------------------------------------------------------------
// Residual + LayerNorm over D=1024.
// ---------------------------------------------------------------------------
__global__ void __launch_bounds__(256)
ln_kernel(const float* __restrict__ emb, const float* __restrict__ att,
          const float* __restrict__ gamma, const float* __restrict__ beta,
          float* __restrict__ out)
{
    __shared__ float shs[8];
    __shared__ float shq[8];
    const size_t base = (size_t)blockIdx.x * DIM;
    const int t = threadIdx.x, lane = t & 31, wrp = t >> 5;

    float4 e = *(const float4*)(emb + base + t * 4);
    float4 a = *(const float4*)(att + base + t * 4);
    float4 x;
    x.x = e.x + a.x; x.y = e.y + a.y; x.z = e.z + a.z; x.w = e.w + a.w;

    float s  = x.x + x.y + x.z + x.w;
    float sq = x.x*x.x + x.y*x.y + x.z*x.z + x.w*x.w;
#pragma unroll
    for (int o = 16; o > 0; o >>= 1) {
        s  += __shfl_xor_sync(0xffffffffu, s,  o);
        sq += __shfl_xor_sync(0xffffffffu, sq, o);
    }
    if (lane == 0) { shs[wrp] = s; shq[wrp] = sq; }
    __syncthreads();
    s = 0.f; sq = 0.f;
#pragma unroll
    for (int w = 0; w < 8; ++w) { s += shs[w]; sq += shq[w]; }

    const float mu   = s * (1.0f / (float)DIM);
    const float var  = sq * (1.0f / (float)DIM) - mu * mu;
    const float rstd = rsqrtf(var + LN_EPS);

    float4 g  = *(const float4*)(gamma + t * 4);
    float4 bt = *(const float4*)(beta  + t * 4);
    float4 r;
    r.x = g.x * (x.x - mu) * rstd + bt.x;
    r.y = g.y * (x.y - mu) * rstd + bt.y;
    r.z = g.z * (x.z - mu) * rstd + bt.z;
    r.w = g.w * (x.w - mu) * rstd + bt.w;
    *(float4*)(out + base + t * 4) = r;
}

// ---------------------------------------------------------------------------
// Launch
// ---------------------------------------------------------------------------
extern "C" void kernel_launch(void* const* d_in, const int* in_sizes, int n_in,
                              void* d_out, int out_size)
{
    (void)in_sizes; (void)n_in; (void)out_size;
    const float* emb   = (const float*)d_in[0];
    const float* Wq    = (const float*)d_in[4];
    const float* bq    = (const float*)d_in[5];
    const float* Wk    = (const float*)d_in[6];
    const float* bk    = (const float*)d_in[7];
    const float* Wv    = (const float*)d_in[8];
    const float* bv    = (const float*)d_in[9];
    const float* gamma = (const float*)d_in[10];
    const float* beta  = (const float*)d_in[11];
    float* out = (float*)d_out;

    void* p;
    __nv_bfloat16 *emb_b, *w_b, *q_b, *k_b, *vt_b, *s_b, *p_b;
    float *att;
    cudaGetSymbolAddress(&p, g_emb_b); emb_b = (__nv_bfloat16*)p;
    cudaGetSymbolAddress(&p, g_w_b);   w_b   = (__nv_bfloat16*)p;
    cudaGetSymbolAddress(&p, g_q_b);   q_b   = (__nv_bfloat16*)p;
    cudaGetSymbolAddress(&p, g_k_b);   k_b   = (__nv_bfloat16*)p;
    cudaGetSymbolAddress(&p, g_vt_b);  vt_b  = (__nv_bfloat16*)p;
    cudaGetSymbolAddress(&p, g_s_b);   s_b   = (__nv_bfloat16*)p;
    cudaGetSymbolAddress(&p, g_p_b);   p_b   = (__nv_bfloat16*)p;
    cudaGetSymbolAddress(&p, g_att);   att   = (float*)p;

    cudaFuncSetAttribute(gemm_mma, cudaFuncAttributeMaxDynamicSharedMemorySize, GEMM_SMEM);

    // Convert inputs to bf16
    const int n4e = MTOT * DIM / 4;
    cvt_kernel<<<(n4e + 255) / 256, 256>>>((const float4*)emb, (uint2*)emb_b, n4e);
    const int n4w = DIM * DIM / 4;
    cvt_kernel<<<(n4w + 255) / 256, 256>>>((const float4*)Wq, (uint2*)(w_b),                 n4w);
    cvt_kernel<<<(n4w + 255) / 256, 256>>>((const float4*)Wk, (uint2*)(w_b + DIM * DIM),     n4w);
    cvt_kernel<<<(n4w + 255) / 256, 256>>>((const float4*)Wv, (uint2*)(w_b + 2 * DIM * DIM), n4w);

    const dim3 blk(256);

    // Q,K projections: [16384,1024] x [1024,1024]^T + bias -> bf16
    const dim3 gq(DIM / TN, MTOT / TM, 1);
    gemm_mma<<<gq, blk, GEMM_SMEM>>>(emb_b, w_b,             bq, 0, nullptr, q_b,
                                     DIM, DIM, DIM, 1.f, 0, 0, 0);
    gemm_mma<<<gq, blk, GEMM_SMEM>>>(emb_b, w_b + DIM * DIM, bk, 0, nullptr, k_b,
                                     DIM, DIM, DIM, 1.f, 0, 0, 0);

    // V^T directly: Vt[d][n] = sum_k Wv[d,k]*emb[n,k] + bv[d]  (bias per row)
    const dim3 gv(MTOT / TN, DIM / TM, 1);
    gemm_mma<<<gv, blk, GEMM_SMEM>>>(w_b + 2 * DIM * DIM, emb_b, bv, 1, nullptr, vt_b,
                                     MTOT, DIM, DIM, 1.f, 0, 0, 0);

    // Scores: per-batch Q @ K^T -> bf16 (scale folded into softmax)
    const dim3 gs(SEQ / TN, SEQ / TM, BATCH);
    gemm_mma<<<gs, blk, GEMM_SMEM>>>(q_b, k_b, nullptr, 0, nullptr, s_b,
                                     SEQ, DIM, DIM, 1.f,
                                     (size_t)SEQ * DIM, (size_t)SEQ * DIM, (size_t)SEQ * SEQ);

    // Softmax rows -> bf16 P
    softmax_kernel<<<MTOT, 256>>>(s_b, p_b);

    // Attended: per-batch P @ V  (B = Vt rows, row stride MTOT, batch col offset SEQ)
    const dim3 gp(DIM / TN, SEQ / TM, BATCH);
    gemm_mma<<<gp, blk, GEMM_SMEM>>>(p_b, vt_b, nullptr, 0, att, nullptr,
                                     DIM, SEQ, MTOT, 1.f,
                                     (size_t)SEQ * SEQ, (size_t)SEQ, (size_t)SEQ * DIM);

    // Residual + LayerNorm
    ln_kernel<<<MTOT, 256>>>(emb, att, gamma, beta, out);
}